// round 8
// baseline (speedup 1.0000x reference)
#include <cuda_runtime.h>
#include <cuda_bf16.h>
#include <math.h>
#include <cstdint>

#define Bv 2
#define Tv 2048
#define NXv 512
#define HDv 128
#define Lv 64
#define KIv 32
#define NN (NXv*NXv)
#define QKW 384   // pruned q/k width (heads 1..3)

// ================= scratch (device globals; no allocation allowed) =================
__device__ float g_v[Bv*Tv*NXv];
__device__ float g_w1 [Bv*4*Tv*Lv];
__device__ float g_w2t[Bv*4*Tv*Lv];
__device__ int   g_cols[Bv*Tv*KIv];
__device__ int   g_cnt [Bv*Tv];
__device__ float g_vpart[8*Bv*NXv];
__device__ float g_scal[2];
__device__ __nv_bfloat16 g_xh[Bv*Tv*NXv], g_xl[Bv*Tv*NXv];
__device__ __nv_bfloat16 g_ah[Bv*Tv*NXv], g_al[Bv*Tv*NXv];
__device__ __nv_bfloat16 g_wh[4*NN], g_wl[4*NN];
__device__ __nv_bfloat16 g_qh[Bv*Tv*QKW], g_ql[Bv*Tv*QKW];
__device__ __nv_bfloat16 g_kh[Bv*Tv*QKW], g_kl[Bv*Tv*QKW];
__device__ __nv_bfloat16 g_skh[Bv*3*Lv*HDv], g_skl[Bv*3*Lv*HDv];
__device__ __nv_bfloat16 g_sqh[Bv*3*Lv*HDv], g_sql[Bv*3*Lv*HDv];

// ================= helpers =================
__device__ __forceinline__ uint32_t smem_u32(const void* p) {
    uint32_t a;
    asm("{ .reg .u64 t; cvta.to.shared.u64 t, %1; cvt.u32.u64 %0, t; }" : "=r"(a) : "l"(p));
    return a;
}
__device__ __forceinline__ uint32_t sw128(uint32_t off) { return off ^ ((off >> 3) & 0x70); }
// 64B-wide rows (4 chunks of 16B): conflict-free chunk permutation
__device__ __forceinline__ uint32_t swz64(int r, int c) {
    return (uint32_t)(r * 64 + ((c ^ ((r >> 1) & 3)) * 16));
}

#define CP16(dst, src)  asm volatile("cp.async.cg.shared.global [%0], [%1], 16;" :: "r"(dst), "l"(src) : "memory")
#define CP_COMMIT()     asm volatile("cp.async.commit_group;" ::: "memory")

#define LDSM4(r, a) \
    asm volatile("ldmatrix.sync.aligned.m8n8.x4.shared.b16 {%0,%1,%2,%3}, [%4];" \
        : "=r"((r)[0]), "=r"((r)[1]), "=r"((r)[2]), "=r"((r)[3]) : "r"(a))

#define MMA16816(d, a, b) \
    asm volatile("mma.sync.aligned.m16n8k16.row.col.f32.bf16.bf16.f32 " \
        "{%0,%1,%2,%3},{%4,%5,%6,%7},{%8,%9},{%0,%1,%2,%3};" \
        : "+f"((d)[0]), "+f"((d)[1]), "+f"((d)[2]), "+f"((d)[3]) \
        : "r"((a)[0]), "r"((a)[1]), "r"((a)[2]), "r"((a)[3]), "r"((b)[0]), "r"((b)[1]))

// ======== NEW qkv mainloop: CTA 128x128, K-chunk 32, 3 stages, warp tile 32x64 ======
// Stage (32KB): Ah@0, Al@8K, Bh@16K, Bl@24K; rows 64B wide, swz64.
#define ST2 32768
#define QKV_SMEM (3*ST2)

__device__ __forceinline__ void mainloop128(
    const __nv_bfloat16* __restrict__ Ah, const __nv_bfloat16* __restrict__ Al,
    const __nv_bfloat16* __restrict__ Bh, const __nv_bfloat16* __restrict__ Bl,
    int m0, char* smem, float acc[2][8][4])
{
    const uint32_t sb = smem_u32(smem);
    const int tid = threadIdx.x, lane = tid & 31;
    const int wid = tid >> 5;
    const int wm = wid & 3, wn = wid >> 2;   // 4(M) x 2(N)

    auto load_stage = [&](int kc, uint32_t dstb) {
        const __nv_bfloat16* bases[4] = {Ah, Al, Bh, Bl};
#pragma unroll
        for (int t = 0; t < 4; ++t) {
            const int rb = (t < 2) ? m0 : 0;
#pragma unroll
            for (int j = 0; j < 2; ++j) {
                int idx = j * 256 + tid;           // 0..511
                int row = idx >> 2, c = idx & 3;
                CP16(dstb + t * 8192 + swz64(row, c),
                     bases[t] + (size_t)(rb + row) * 512 + kc * 32 + c * 8);
            }
        }
    };

    load_stage(0, sb);             CP_COMMIT();
    load_stage(1, sb + ST2);       CP_COMMIT();

    for (int kc = 0; kc < 16; ++kc) {
        if (kc < 14) {
            load_stage(kc + 2, sb + ((kc + 2) % 3) * ST2);
            CP_COMMIT();
            asm volatile("cp.async.wait_group 2;" ::: "memory");
        } else if (kc == 14) {
            asm volatile("cp.async.wait_group 1;" ::: "memory");
        } else {
            asm volatile("cp.async.wait_group 0;" ::: "memory");
        }
        __syncthreads();
        const uint32_t sbuf = sb + (kc % 3) * ST2;

#pragma unroll
        for (int kk = 0; kk < 2; ++kk) {
            const int klo = kk * 2;
            uint32_t ah[2][4], al[2][4];
            const int arow = ((lane >> 3) & 1) * 8 + (lane & 7);
            const int achk = klo + (lane >> 4);
#pragma unroll
            for (int f = 0; f < 2; ++f) {
                const int row = wm * 32 + f * 16 + arow;
                LDSM4(ah[f], sbuf + swz64(row, achk));
                LDSM4(al[f], sbuf + 8192 + swz64(row, achk));
            }
            const int brow = (lane >> 4) * 8 + (lane & 7);
            const int bchk = klo + ((lane >> 3) & 1);
#pragma unroll
            for (int p = 0; p < 4; ++p) {
                const int row = wn * 64 + p * 16 + brow;
                uint32_t r[4], s[4];
                LDSM4(r, sbuf + 16384 + swz64(row, bchk));
                LDSM4(s, sbuf + 24576 + swz64(row, bchk));
#pragma unroll
                for (int f = 0; f < 2; ++f) {
                    MMA16816(acc[f][2*p],   ah[f], r);
                    MMA16816(acc[f][2*p],   ah[f], s);
                    MMA16816(acc[f][2*p],   al[f], r);
                    MMA16816(acc[f][2*p+1], ah[f], r+2);
                    MMA16816(acc[f][2*p+1], ah[f], s+2);
                    MMA16816(acc[f][2*p+1], al[f], r+2);
                }
            }
        }
        __syncthreads();
    }
}

// Fused q/k/v projection. grid (32, 10):
//  y 0..2 : q cols 128..511 -> bf16 (hi,lo) pruned [4096, 384]
//  y 3..5 : k cols 128..511 -> bf16 (hi,lo) pruned
//  y 6..9 : v cols 0..511   -> fp32
__global__ void __launch_bounds__(256, 2) gemm_qkv()
{
    extern __shared__ char smem[];
    const int y = blockIdx.y;
    int widx, slab;
    if (y < 3)      { widx = 0; slab = 128 + y * 128; }
    else if (y < 6) { widx = 1; slab = 128 + (y - 3) * 128; }
    else            { widx = 2; slab = (y - 6) * 128; }
    const int m0 = blockIdx.x * 128;

    float acc[2][8][4] = {};
    mainloop128(g_xh, g_xl,
                g_wh + (size_t)widx * NN + (size_t)slab * 512,
                g_wl + (size_t)widx * NN + (size_t)slab * 512,
                m0, smem, acc);

    const int tid = threadIdx.x, lane = tid & 31;
    const int wid = tid >> 5;
    const int wm = wid & 3, wn = wid >> 2;
    const int r0 = m0 + wm * 32 + (lane >> 2);
    const int c0 = wn * 64 + (lane & 3) * 2;

    if (y < 6) {
        __nv_bfloat16* dh = widx ? g_kh : g_qh;
        __nv_bfloat16* dl = widx ? g_kl : g_ql;
        const int cp0 = (slab - 128) + c0;
#pragma unroll
        for (int f = 0; f < 2; ++f)
#pragma unroll
            for (int n = 0; n < 8; ++n) {
#pragma unroll
                for (int hr = 0; hr < 2; ++hr) {
                    const int row = r0 + f * 16 + hr * 8;
                    float v0 = acc[f][n][hr*2], v1 = acc[f][n][hr*2+1];
                    __nv_bfloat16 h0 = __float2bfloat16(v0), h1 = __float2bfloat16(v1);
                    size_t o = (size_t)row * QKW + cp0 + n * 8;
                    *(__nv_bfloat162*)(dh + o) = __halves2bfloat162(h0, h1);
                    *(__nv_bfloat162*)(dl + o) = __halves2bfloat162(
                        __float2bfloat16(v0 - __bfloat162float(h0)),
                        __float2bfloat16(v1 - __bfloat162float(h1)));
                }
            }
    } else {
#pragma unroll
        for (int f = 0; f < 2; ++f)
#pragma unroll
            for (int n = 0; n < 8; ++n) {
                float* p0 = g_v + (size_t)(r0 + f * 16) * 512 + slab + c0 + n * 8;
                *(float2*)p0 = make_float2(acc[f][n][0], acc[f][n][1]);
                *(float2*)(p0 + 8 * 512) = make_float2(acc[f][n][2], acc[f][n][3]);
            }
    }
}

// ================= 64x128 mainloop (K=64 chunks, 2 stages) — gemm_out ==============
#define STAGE_BYTES 49152
#define GEMM_SMEM_TOTAL (2*STAGE_BYTES)

__device__ __forceinline__ void mainloop64(
    const __nv_bfloat16* __restrict__ Ah, const __nv_bfloat16* __restrict__ Al,
    const __nv_bfloat16* __restrict__ Bh, const __nv_bfloat16* __restrict__ Bl,
    int m0, char* smem, float acc[2][4][4])
{
    const uint32_t sb = smem_u32(smem);
    const int tid = threadIdx.x, lane = tid & 31;
    const int wid = tid >> 5;
    const int wm = wid & 1, wn = wid >> 1;

    auto load_stage = [&](int kc, uint32_t dstb) {
#pragma unroll
        for (int t = 0; t < 2; ++t) {
            const __nv_bfloat16* base = t ? Al : Ah;
#pragma unroll
            for (int j = 0; j < 2; ++j) {
                int idx = j * 256 + tid;
                int row = idx >> 3, c = idx & 7;
                CP16(dstb + t * 8192 + sw128((uint32_t)(row * 128 + c * 16)),
                     base + (size_t)(m0 + row) * 512 + kc * 64 + c * 8);
            }
        }
#pragma unroll
        for (int t = 0; t < 2; ++t) {
            const __nv_bfloat16* base = t ? Bl : Bh;
#pragma unroll
            for (int j = 0; j < 4; ++j) {
                int idx = j * 256 + tid;
                int row = idx >> 3, c = idx & 7;
                CP16(dstb + 16384 + t * 16384 + sw128((uint32_t)(row * 128 + c * 16)),
                     base + (size_t)row * 512 + kc * 64 + c * 8);
            }
        }
    };

    load_stage(0, sb);
    CP_COMMIT();

    for (int kc = 0; kc < 8; ++kc) {
        if (kc < 7) {
            load_stage(kc + 1, sb + ((kc + 1) & 1) * STAGE_BYTES);
            CP_COMMIT();
            asm volatile("cp.async.wait_group 1;" ::: "memory");
        } else {
            asm volatile("cp.async.wait_group 0;" ::: "memory");
        }
        __syncthreads();
        const uint32_t sbuf = sb + (kc & 1) * STAGE_BYTES;

#pragma unroll
        for (int kk = 0; kk < 4; ++kk) {
            const int klo = kk * 2;
            uint32_t ah[2][4], al[2][4], bh[4][2], bl[4][2];
            const int arow = ((lane >> 3) & 1) * 8 + (lane & 7);
            const int achk = klo + (lane >> 4);
#pragma unroll
            for (int f = 0; f < 2; ++f) {
                uint32_t off = sw128((uint32_t)((wm * 32 + f * 16 + arow) * 128 + achk * 16));
                LDSM4(ah[f], sbuf + off);
                LDSM4(al[f], sbuf + 8192 + off);
            }
            const int brow = (lane >> 4) * 8 + (lane & 7);
            const int bchk = klo + ((lane >> 3) & 1);
#pragma unroll
            for (int p = 0; p < 2; ++p) {
                uint32_t off = sw128((uint32_t)((wn * 32 + p * 16 + brow) * 128 + bchk * 16));
                uint32_t r[4];
                LDSM4(r, sbuf + 16384 + off);
                bh[2*p][0] = r[0]; bh[2*p][1] = r[1];
                bh[2*p+1][0] = r[2]; bh[2*p+1][1] = r[3];
                LDSM4(r, sbuf + 32768 + off);
                bl[2*p][0] = r[0]; bl[2*p][1] = r[1];
                bl[2*p+1][0] = r[2]; bl[2*p+1][1] = r[3];
            }
#pragma unroll
            for (int f = 0; f < 2; ++f)
#pragma unroll
                for (int n = 0; n < 4; ++n) {
                    MMA16816(acc[f][n], ah[f], bh[n]);
                    MMA16816(acc[f][n], ah[f], bl[n]);
                    MMA16816(acc[f][n], al[f], bh[n]);
                }
        }
        __syncthreads();
    }
}

// Output projection: out = a @ wo^T. grid (64, 4).
__global__ void __launch_bounds__(256, 2) gemm_out(float* __restrict__ out)
{
    extern __shared__ char smem[];
    const int brow = blockIdx.y * 128;
    const int m0 = blockIdx.x * 64;
    float acc[2][4][4] = {};
    mainloop64(g_ah, g_al,
               g_wh + 3ull * NN + (size_t)brow * 512,
               g_wl + 3ull * NN + (size_t)brow * 512,
               m0, smem, acc);
    const int tid = threadIdx.x, lane = tid & 31;
    const int wid = tid >> 5;
    const int wm = wid & 1, wn = wid >> 1;
    const int r0 = m0 + wm * 32 + (lane >> 2);
    const int c0 = brow + wn * 32 + (lane & 3) * 2;
#pragma unroll
    for (int f = 0; f < 2; ++f)
#pragma unroll
        for (int n = 0; n < 4; ++n) {
            float* p0 = out + (size_t)(r0 + f * 16) * 512 + c0 + n * 8;
            *(float2*)p0 = make_float2(acc[f][n][0], acc[f][n][1]);
            *(float2*)(p0 + 8 * 512) = make_float2(acc[f][n][2], acc[f][n][3]);
        }
}

// ================= gemm_w via MMA: w1 = q.sk^T, w2t = k.sq^T ======================
#define GW_SMEM (2*49152)
__global__ void __launch_bounds__(256, 2) gemm_w_mma()
{
    extern __shared__ char smem[];
    const uint32_t sb = smem_u32(smem);
    const int tid = threadIdx.x, lane = tid & 31;
    const int wm = (tid >> 5) & 3, wn = tid >> 7;
    const int second = blockIdx.z;
    const int bh_ = blockIdx.y;
    const int b = bh_ / 3, hm = bh_ % 3;
    const int m0 = blockIdx.x * 128;

    const __nv_bfloat16* Ah = (second ? g_kh : g_qh) + (size_t)b*Tv*QKW + hm*HDv;
    const __nv_bfloat16* Al = (second ? g_kl : g_ql) + (size_t)b*Tv*QKW + hm*HDv;
    const __nv_bfloat16* Bh = (second ? g_sqh : g_skh) + (size_t)bh_*Lv*HDv;
    const __nv_bfloat16* Bl = (second ? g_sql : g_skl) + (size_t)bh_*Lv*HDv;
    float* C = (second ? g_w2t : g_w1) + ((size_t)((b*4+hm+1)*Tv) + m0) * Lv;

    float acc[2][4][4] = {};

    auto load_stage = [&](int kc, uint32_t dstb) {
#pragma unroll
        for (int t = 0; t < 2; ++t) {
            const __nv_bfloat16* base = t ? Al : Ah;
#pragma unroll
            for (int j = 0; j < 4; ++j) {
                int idx = j * 256 + tid;
                int row = idx >> 3, c = idx & 7;
                CP16(dstb + t * 16384 + sw128((uint32_t)(row * 128 + c * 16)),
                     base + (size_t)(m0 + row) * QKW + kc * 64 + c * 8);
            }
        }
#pragma unroll
        for (int t = 0; t < 2; ++t) {
            const __nv_bfloat16* base = t ? Bl : Bh;
#pragma unroll
            for (int j = 0; j < 2; ++j) {
                int idx = j * 256 + tid;
                int row = idx >> 3, c = idx & 7;
                CP16(dstb + 32768 + t * 8192 + sw128((uint32_t)(row * 128 + c * 16)),
                     base + (size_t)row * HDv + kc * 64 + c * 8);
            }
        }
    };

    load_stage(0, sb); CP_COMMIT();
    load_stage(1, sb + 49152); CP_COMMIT();

    for (int kc = 0; kc < 2; ++kc) {
        if (kc == 0) asm volatile("cp.async.wait_group 1;" ::: "memory");
        else         asm volatile("cp.async.wait_group 0;" ::: "memory");
        __syncthreads();
        const uint32_t sbuf = sb + kc * 49152;
#pragma unroll
        for (int kk = 0; kk < 4; ++kk) {
            const int klo = kk * 2;
            uint32_t ah[2][4], al[2][4], bh[4][2], bl[4][2];
            const int arow = ((lane >> 3) & 1) * 8 + (lane & 7);
            const int achk = klo + (lane >> 4);
#pragma unroll
            for (int f = 0; f < 2; ++f) {
                uint32_t off = sw128((uint32_t)((wm * 32 + f * 16 + arow) * 128 + achk * 16));
                LDSM4(ah[f], sbuf + off);
                LDSM4(al[f], sbuf + 16384 + off);
            }
            const int brow = (lane >> 4) * 8 + (lane & 7);
            const int bchk = klo + ((lane >> 3) & 1);
#pragma unroll
            for (int p = 0; p < 2; ++p) {
                uint32_t off = sw128((uint32_t)((wn * 32 + p * 16 + brow) * 128 + bchk * 16));
                uint32_t r[4];
                LDSM4(r, sbuf + 32768 + off);
                bh[2*p][0] = r[0]; bh[2*p][1] = r[1];
                bh[2*p+1][0] = r[2]; bh[2*p+1][1] = r[3];
                LDSM4(r, sbuf + 40960 + off);
                bl[2*p][0] = r[0]; bl[2*p][1] = r[1];
                bl[2*p+1][0] = r[2]; bl[2*p+1][1] = r[3];
            }
#pragma unroll
            for (int f = 0; f < 2; ++f)
#pragma unroll
                for (int n = 0; n < 4; ++n) {
                    MMA16816(acc[f][n], ah[f], bh[n]);
                    MMA16816(acc[f][n], ah[f], bl[n]);
                    MMA16816(acc[f][n], al[f], bh[n]);
                }
        }
        __syncthreads();
    }

    const int r0 = wm * 32 + (lane >> 2);
    const int c0 = wn * 32 + (lane & 3) * 2;
#pragma unroll
    for (int f = 0; f < 2; ++f)
#pragma unroll
        for (int n = 0; n < 4; ++n) {
            float* p0 = C + (size_t)(r0 + f * 16) * Lv + c0 + n * 8;
            *(float2*)p0 = make_float2(acc[f][n][0], acc[f][n][1]);
            *(float2*)(p0 + 8 * Lv) = make_float2(acc[f][n][2], acc[f][n][3]);
        }
}

// ================= fused fp32 -> (hi,lo) bf16 split (x + 4 weights) =================
__global__ void split_all(const float2* __restrict__ x,
                          const float2* __restrict__ w0, const float2* __restrict__ w1,
                          const float2* __restrict__ w2, const float2* __restrict__ w3)
{
    int bid = blockIdx.x;
    const float2* src;
    __nv_bfloat162 *dh, *dl;
    size_t i;
    if (bid < 4096) {
        i = (size_t)bid * 256 + threadIdx.x;
        src = x; dh = (__nv_bfloat162*)g_xh; dl = (__nv_bfloat162*)g_xl;
    } else {
        int r = bid - 4096;
        int widx = r >> 9;
        i = (size_t)(r & 511) * 256 + threadIdx.x;
        src = (widx == 0) ? w0 : (widx == 1) ? w1 : (widx == 2) ? w2 : w3;
        dh = (__nv_bfloat162*)g_wh + (size_t)widx * (NN/2);
        dl = (__nv_bfloat162*)g_wl + (size_t)widx * (NN/2);
    }
    float2 v = src[i];
    __nv_bfloat16 h0 = __float2bfloat16(v.x);
    __nv_bfloat16 h1 = __float2bfloat16(v.y);
    dh[i] = __halves2bfloat162(h0, h1);
    dl[i] = __halves2bfloat162(__float2bfloat16(v.x - __bfloat162float(h0)),
                               __float2bfloat16(v.y - __bfloat162float(h1)));
}

// ================= lam scalar =================
__global__ void lam_kernel(const float* __restrict__ lq1, const float* __restrict__ lk1,
                           const float* __restrict__ lq2, const float* __restrict__ lk2,
                           const int* __restrict__ lptr)
{
    __shared__ float r1[128], r2[128];
    int t = threadIdx.x;
    r1[t] = lq1[t]*lk1[t];
    r2[t] = lq2[t]*lk2[t];
    __syncthreads();
    for (int o = 64; o; o >>= 1) {
        if (t < o) { r1[t] += r1[t+o]; r2[t] += r2[t+o]; }
        __syncthreads();
    }
    if (t == 0) {
        float lam_init = 0.8f - 0.6f*expf(-0.3f*(float)lptr[0]);
        g_scal[0] = expf(r1[0]) - expf(r2[0]) + lam_init;
        g_scal[1] = 1.0f - lam_init;
    }
}

// ================= sq / sk: warp-per-task reconstruct+normalize+scale+split ========
__global__ void __launch_bounds__(256) sqsk_kernel(const int* __restrict__ landmark,
                                                   const float* __restrict__ m1,
                                                   const float* __restrict__ m2)
{
    int task = blockIdx.x * 8 + (threadIdx.x >> 5);
    int lane = threadIdx.x & 31;
    int which = task & 1;
    int rest = task >> 1;
    int j  = rest & 63;
    int hm = (rest >> 6) % 3;
    int b  = rest / 192;
    int tok = landmark[j];

    size_t off = (size_t)(b*Tv + tok)*QKW + hm*HDv + lane*4;
    const __nv_bfloat16* ph = which ? g_kh : g_qh;
    const __nv_bfloat16* pl = which ? g_kl : g_ql;
    float v[4];
#pragma unroll
    for (int e = 0; e < 4; ++e)
        v[e] = __bfloat162float(ph[off+e]) + __bfloat162float(pl[off+e]);

    float ss = v[0]*v[0] + v[1]*v[1] + v[2]*v[2] + v[3]*v[3];
#pragma unroll
    for (int o = 16; o; o >>= 1) ss += __shfl_xor_sync(0xffffffffu, ss, o);

    float scale = (which ? m2[(hm+1)*Lv + j] : m1[(hm+1)*Lv + j]) * rsqrtf(ss);
    __nv_bfloat16* dh = which ? g_skh : g_sqh;
    __nv_bfloat16* dl = which ? g_skl : g_sql;
    size_t d = ((size_t)(b*3 + hm)*Lv + j)*HDv + lane*4;
#pragma unroll
    for (int e = 0; e < 4; ++e) {
        float o = v[e] * scale;
        __nv_bfloat16 h = __float2bfloat16(o);
        dh[d+e] = h;
        dl[d+e] = __float2bfloat16(o - __bfloat162float(h));
    }
}

// ================= symmetric mask -> per-row CSR =================
__global__ void mask_kernel(const int* __restrict__ rns)
{
    int warp = (blockIdx.x * blockDim.x + threadIdx.x) >> 5;
    int lane = threadIdx.x & 31;
    int b = warp >> 11, i = warp & (Tv-1);
    const int* row = rns + (size_t)warp * KIv;
    int j = row[lane];
    bool dup = false;
#pragma unroll
    for (int k2 = 0; k2 < 32; ++k2) {
        int jj = __shfl_sync(0xffffffffu, j, k2);
        if (k2 < lane && jj == j) dup = true;
    }
    bool mem = false;
    const int* rj = rns + (size_t)(b*Tv + j)*KIv;
#pragma unroll
    for (int m = 0; m < 32; ++m) if (rj[m] == i) mem = true;
    bool valid = (!dup) && mem;
    unsigned bal = __ballot_sync(0xffffffffu, valid);
    if (valid) {
        int pos = __popc(bal & ((1u << lane) - 1u));
        g_cols[(size_t)warp*KIv + pos] = j;
    }
    if (lane == 0) g_cnt[warp] = __popc(bal);
}

// ================= column partial sums of v (zero-nnz rows) =================
__global__ void colsumA()
{
    int g = blockIdx.x*256 + threadIdx.x;
    int chunk = g >> 10;
    int c = g & 1023;
    int b = c >> 9, col = c & 511;
    const float* p = g_v + (size_t)(b*Tv + chunk*256)*NXv + col;
    float s = 0.f;
    for (int t = 0; t < 256; ++t) s += p[(size_t)t*NXv];
    g_vpart[g] = s;
}

// ================= sparse attention rows + wmix + RMSNorm + bf16 split ===========
__global__ void __launch_bounds__(256) attn_rows(const float* __restrict__ rms_g)
{
    const int r = blockIdx.x;
    const int b = r >> 11;
    const int i = r & (Tv-1);
    const int tid = threadIdx.x;
    __shared__ int   scols[KIv];
    __shared__ float sw[3][KIv];
    __shared__ float c0[KIv], c1[KIv];
    __shared__ float red[512];
    const int cnt = g_cnt[r];
    if (tid < KIv && tid < cnt) scols[tid] = g_cols[(size_t)r*KIv + tid];
    __syncthreads();
    const float lam = g_scal[0];
    const int wid = tid >> 5, lane = tid & 31;

    for (int task = wid; task < 3*cnt; task += 8) {
        int hm = task % 3, j = task / 3, h = hm + 1;
        const float* w1p = g_w1  + ((size_t)((b*4+h)*Tv + i)        << 6);
        const float* w2p = g_w2t + ((size_t)((b*4+h)*Tv + scols[j]) << 6);
        float s = w1p[lane]*w2p[lane] + w1p[lane+32]*w2p[lane+32];
#pragma unroll
        for (int o = 16; o; o >>= 1) s += __shfl_xor_sync(0xffffffffu, s, o);
        if (lane == 0) sw[hm][j] = s;
    }
    __syncthreads();

    if (wid == 0 && cnt > 0) {
        float p[3];
#pragma unroll
        for (int hm = 0; hm < 3; ++hm) {
            float x = (lane < cnt) ? sw[hm][lane] : -INFINITY;
            float mx = x;
#pragma unroll
            for (int o = 16; o; o >>= 1) mx = fmaxf(mx, __shfl_xor_sync(0xffffffffu, mx, o));
            float e = (lane < cnt) ? expf(x - mx) : 0.f;
            float sm = e;
#pragma unroll
            for (int o = 16; o; o >>= 1) sm += __shfl_xor_sync(0xffffffffu, sm, o);
            p[hm] = e / sm;
        }
        if (lane < cnt) {
            c0[lane] = (1.f - lam)*p[1] - lam*p[0];
            c1[lane] = p[1] - p[0] + (1.f - 2.f*lam)*p[2];
        }
    }
    __syncthreads();

    float s0 = 0.f, s1 = 0.f;
    if (cnt > 0) {
#pragma unroll 4
        for (int j = 0; j < cnt; ++j) {
            const float* vp = g_v + ((size_t)(b*Tv + scols[j]) << 9);
            s0 += c0[j] * vp[tid];
            s1 += c1[j] * vp[tid + 256];
        }
    } else {
        float u = (1.f - 2.f*lam) * (1.f/(float)Tv);
        float t0 = 0.f, t1 = 0.f;
#pragma unroll
        for (int ch = 0; ch < 8; ++ch) {
            t0 += g_vpart[ch*1024 + b*512 + tid];
            t1 += g_vpart[ch*1024 + b*512 + tid + 256];
        }
        s0 = u * t0;
        s1 = u * t1;
    }

    red[tid]       = s0*s0;
    red[tid + 256] = s1*s1;
    __syncthreads();
#pragma unroll
    for (int o = 128; o; o >>= 1) {
        if (tid < o) { red[tid] += red[tid+o]; red[256+tid] += red[256+tid+o]; }
        __syncthreads();
    }
    float onem = g_scal[1];
    float g = rms_g[tid];
    float a0 = s0 * rsqrtf(red[0]  *(1.f/256.f) + 1e-5f) * g * onem;
    float a1 = s1 * rsqrtf(red[256]*(1.f/256.f) + 1e-5f) * g * onem;
    __nv_bfloat16 h0 = __float2bfloat16(a0);
    __nv_bfloat16 h1 = __float2bfloat16(a1);
    size_t o0 = (size_t)r*NXv + tid, o1 = o0 + 256;
    g_ah[o0] = h0;                                   g_ah[o1] = h1;
    g_al[o0] = __float2bfloat16(a0 - __bfloat162float(h0));
    g_al[o1] = __float2bfloat16(a1 - __bfloat162float(h1));
}

// ================= launch (multi-stream fork/join, graph-capture safe) =============
extern "C" void kernel_launch(void* const* d_in, const int* in_sizes, int n_in,
                              void* d_out, int out_size)
{
    const float* x    = (const float*)d_in[0];
    const float* wq   = (const float*)d_in[1];
    const float* wk   = (const float*)d_in[2];
    const float* wv   = (const float*)d_in[3];
    const float* wo   = (const float*)d_in[4];
    const float* m1   = (const float*)d_in[5];
    const float* m2   = (const float*)d_in[6];
    const float* lq1  = (const float*)d_in[7];
    const float* lk1  = (const float*)d_in[8];
    const float* lq2  = (const float*)d_in[9];
    const float* lk2  = (const float*)d_in[10];
    const float* rmsg = (const float*)d_in[11];
    const int*   lp   = (const int*)d_in[12];
    const int*   rns  = (const int*)d_in[14];
    const int*   lmk  = (const int*)d_in[15];
    float* out = (float*)d_out;

    static cudaStream_t s1 = nullptr, s2 = nullptr;
    static cudaEvent_t e_fork = nullptr, e_mask = nullptr, e_qkv = nullptr, e_cols = nullptr;
    static int inited = 0;
    if (!inited) {
        cudaStreamCreateWithFlags(&s1, cudaStreamNonBlocking);
        cudaStreamCreateWithFlags(&s2, cudaStreamNonBlocking);
        cudaEventCreateWithFlags(&e_fork, cudaEventDisableTiming);
        cudaEventCreateWithFlags(&e_mask, cudaEventDisableTiming);
        cudaEventCreateWithFlags(&e_qkv,  cudaEventDisableTiming);
        cudaEventCreateWithFlags(&e_cols, cudaEventDisableTiming);
        cudaFuncSetAttribute(gemm_qkv,   cudaFuncAttributeMaxDynamicSharedMemorySize, QKV_SMEM);
        cudaFuncSetAttribute(gemm_out,   cudaFuncAttributeMaxDynamicSharedMemorySize, GEMM_SMEM_TOTAL);
        cudaFuncSetAttribute(gemm_w_mma, cudaFuncAttributeMaxDynamicSharedMemorySize, GW_SMEM);
        inited = 1;
    }

    // fork: lam + mask depend only on kernel inputs -> run on s1 concurrently
    cudaEventRecord(e_fork, 0);
    cudaStreamWaitEvent(s1, e_fork, 0);
    lam_kernel<<<1, 128, 0, s1>>>(lq1, lk1, lq2, lk2, lp);
    mask_kernel<<<Bv*Tv*32/256, 256, 0, s1>>>(rns);
    cudaEventRecord(e_mask, s1);

    // main chain
    split_all<<<6144, 256>>>((const float2*)x, (const float2*)wq, (const float2*)wk,
                             (const float2*)wv, (const float2*)wo);
    gemm_qkv<<<dim3(Bv*Tv/128, 10), 256, QKV_SMEM>>>();
    cudaEventRecord(e_qkv, 0);

    // fork: colsumA on s2 concurrent with sqsk -> gemm_w on main
    cudaStreamWaitEvent(s2, e_qkv, 0);
    colsumA<<<32, 256, 0, s2>>>();
    cudaEventRecord(e_cols, s2);

    sqsk_kernel<<<96, 256>>>(lmk, m1, m2);
    gemm_w_mma<<<dim3(Tv/128, Bv*3, 2), 256, GW_SMEM>>>();

    // join
    cudaStreamWaitEvent(0, e_mask, 0);
    cudaStreamWaitEvent(0, e_cols, 0);
    attn_rows<<<Bv*Tv, 256>>>(rmsg);
    gemm_out<<<dim3(Bv*Tv/64, 4), 256, GEMM_SMEM_TOTAL>>>(out);
}

// round 9
// speedup vs baseline: 1.1170x; 1.1170x over previous
#include <cuda_runtime.h>
#include <cuda_bf16.h>
#include <math.h>
#include <cstdint>

#define Bv 2
#define Tv 2048
#define NXv 512
#define HDv 128
#define Lv 64
#define KIv 32
#define NN (NXv*NXv)
#define QKW 384   // pruned q/k width (heads 1..3)

// ================= scratch (device globals; no allocation allowed) =================
__device__ float g_v[Bv*Tv*NXv];
__device__ float g_w1 [Bv*4*Tv*Lv];
__device__ float g_w2t[Bv*4*Tv*Lv];
__device__ int   g_cols[Bv*Tv*KIv];
__device__ int   g_cnt [Bv*Tv];
__device__ float g_vpart[8*Bv*NXv];
__device__ float g_scal[2];
__device__ __nv_bfloat16 g_xh[Bv*Tv*NXv], g_xl[Bv*Tv*NXv];
__device__ __nv_bfloat16 g_ah[Bv*Tv*NXv], g_al[Bv*Tv*NXv];
__device__ __nv_bfloat16 g_wh[4*NN], g_wl[4*NN];
__device__ __nv_bfloat16 g_qh[Bv*Tv*QKW], g_ql[Bv*Tv*QKW];
__device__ __nv_bfloat16 g_kh[Bv*Tv*QKW], g_kl[Bv*Tv*QKW];
__device__ __nv_bfloat16 g_skh[Bv*3*Lv*HDv], g_skl[Bv*3*Lv*HDv];
__device__ __nv_bfloat16 g_sqh[Bv*3*Lv*HDv], g_sql[Bv*3*Lv*HDv];

// ================= helpers =================
__device__ __forceinline__ uint32_t smem_u32(const void* p) {
    uint32_t a;
    asm("{ .reg .u64 t; cvta.to.shared.u64 t, %1; cvt.u32.u64 %0, t; }" : "=r"(a) : "l"(p));
    return a;
}
__device__ __forceinline__ uint32_t sw128(uint32_t off) { return off ^ ((off >> 3) & 0x70); }

#define CP16(dst, src)  asm volatile("cp.async.cg.shared.global [%0], [%1], 16;" :: "r"(dst), "l"(src) : "memory")
#define CP_COMMIT()     asm volatile("cp.async.commit_group;" ::: "memory")

#define LDSM4(r, a) \
    asm volatile("ldmatrix.sync.aligned.m8n8.x4.shared.b16 {%0,%1,%2,%3}, [%4];" \
        : "=r"((r)[0]), "=r"((r)[1]), "=r"((r)[2]), "=r"((r)[3]) : "r"(a))

#define MMA16816(d, a, b) \
    asm volatile("mma.sync.aligned.m16n8k16.row.col.f32.bf16.bf16.f32 " \
        "{%0,%1,%2,%3},{%4,%5,%6,%7},{%8,%9},{%0,%1,%2,%3};" \
        : "+f"((d)[0]), "+f"((d)[1]), "+f"((d)[2]), "+f"((d)[3]) \
        : "r"((a)[0]), "r"((a)[1]), "r"((a)[2]), "r"((a)[3]), "r"((b)[0]), "r"((b)[1]))

// ================= 256-thread split-bf16 MMA mainloop: 64x128 tile, K=512 ==========
// (Round-7 proven version: warp grid 2x4, warp tile 32x32, 2 stages of 48KB)
#define STAGE_BYTES 49152
#define GEMM_SMEM_TOTAL (2*STAGE_BYTES)

__device__ __forceinline__ void mainloop64(
    const __nv_bfloat16* __restrict__ Ah, const __nv_bfloat16* __restrict__ Al,
    const __nv_bfloat16* __restrict__ Bh, const __nv_bfloat16* __restrict__ Bl,
    int m0, char* smem, float acc[2][4][4])
{
    const uint32_t sb = smem_u32(smem);
    const int tid = threadIdx.x, lane = tid & 31;
    const int wid = tid >> 5;
    const int wm = wid & 1, wn = wid >> 1;

    auto load_stage = [&](int kc, uint32_t dstb) {
#pragma unroll
        for (int t = 0; t < 2; ++t) {
            const __nv_bfloat16* base = t ? Al : Ah;
#pragma unroll
            for (int j = 0; j < 2; ++j) {
                int idx = j * 256 + tid;
                int row = idx >> 3, c = idx & 7;
                CP16(dstb + t * 8192 + sw128((uint32_t)(row * 128 + c * 16)),
                     base + (size_t)(m0 + row) * 512 + kc * 64 + c * 8);
            }
        }
#pragma unroll
        for (int t = 0; t < 2; ++t) {
            const __nv_bfloat16* base = t ? Bl : Bh;
#pragma unroll
            for (int j = 0; j < 4; ++j) {
                int idx = j * 256 + tid;
                int row = idx >> 3, c = idx & 7;
                CP16(dstb + 16384 + t * 16384 + sw128((uint32_t)(row * 128 + c * 16)),
                     base + (size_t)row * 512 + kc * 64 + c * 8);
            }
        }
    };

    load_stage(0, sb);
    CP_COMMIT();

    for (int kc = 0; kc < 8; ++kc) {
        if (kc < 7) {
            load_stage(kc + 1, sb + ((kc + 1) & 1) * STAGE_BYTES);
            CP_COMMIT();
            asm volatile("cp.async.wait_group 1;" ::: "memory");
        } else {
            asm volatile("cp.async.wait_group 0;" ::: "memory");
        }
        __syncthreads();
        const uint32_t sbuf = sb + (kc & 1) * STAGE_BYTES;

#pragma unroll
        for (int kk = 0; kk < 4; ++kk) {
            const int klo = kk * 2;
            uint32_t ah[2][4], al[2][4], bh[4][2], bl[4][2];
            const int arow = ((lane >> 3) & 1) * 8 + (lane & 7);
            const int achk = klo + (lane >> 4);
#pragma unroll
            for (int f = 0; f < 2; ++f) {
                uint32_t off = sw128((uint32_t)((wm * 32 + f * 16 + arow) * 128 + achk * 16));
                LDSM4(ah[f], sbuf + off);
                LDSM4(al[f], sbuf + 8192 + off);
            }
            const int brow = (lane >> 4) * 8 + (lane & 7);
            const int bchk = klo + ((lane >> 3) & 1);
#pragma unroll
            for (int p = 0; p < 2; ++p) {
                uint32_t off = sw128((uint32_t)((wn * 32 + p * 16 + brow) * 128 + bchk * 16));
                uint32_t r[4];
                LDSM4(r, sbuf + 16384 + off);
                bh[2*p][0] = r[0]; bh[2*p][1] = r[1];
                bh[2*p+1][0] = r[2]; bh[2*p+1][1] = r[3];
                LDSM4(r, sbuf + 32768 + off);
                bl[2*p][0] = r[0]; bl[2*p][1] = r[1];
                bl[2*p+1][0] = r[2]; bl[2*p+1][1] = r[3];
            }
#pragma unroll
            for (int f = 0; f < 2; ++f)
#pragma unroll
                for (int n = 0; n < 4; ++n) {
                    MMA16816(acc[f][n], ah[f], bh[n]);
                    MMA16816(acc[f][n], ah[f], bl[n]);
                    MMA16816(acc[f][n], al[f], bh[n]);
                }
        }
        __syncthreads();
    }
}

// q/k projection. grid (64, 6): y 0..2 q slabs 128.., y 3..5 k slabs 128..
__global__ void __launch_bounds__(256, 2) gemm_qk()
{
    extern __shared__ char smem[];
    const int y = blockIdx.y;
    const int widx = (y < 3) ? 0 : 1;
    const int slab = 128 + (y % 3) * 128;
    const int m0 = blockIdx.x * 64;

    float acc[2][4][4] = {};
    mainloop64(g_xh, g_xl,
               g_wh + (size_t)widx * NN + (size_t)slab * 512,
               g_wl + (size_t)widx * NN + (size_t)slab * 512,
               m0, smem, acc);

    const int tid = threadIdx.x, lane = tid & 31;
    const int wid = tid >> 5;
    const int wm = wid & 1, wn = wid >> 1;
    const int r0 = m0 + wm * 32 + (lane >> 2);
    const int c0 = wn * 32 + (lane & 3) * 2;

    __nv_bfloat16* dh = widx ? g_kh : g_qh;
    __nv_bfloat16* dl = widx ? g_kl : g_ql;
    const int cp0 = (slab - 128) + c0;
#pragma unroll
    for (int f = 0; f < 2; ++f)
#pragma unroll
        for (int n = 0; n < 4; ++n) {
#pragma unroll
            for (int hr = 0; hr < 2; ++hr) {
                const int row = r0 + f * 16 + hr * 8;
                float v0 = acc[f][n][hr*2], v1 = acc[f][n][hr*2+1];
                __nv_bfloat16 h0 = __float2bfloat16(v0), h1 = __float2bfloat16(v1);
                size_t o = (size_t)row * QKW + cp0 + n * 8;
                *(__nv_bfloat162*)(dh + o) = __halves2bfloat162(h0, h1);
                *(__nv_bfloat162*)(dl + o) = __halves2bfloat162(
                    __float2bfloat16(v0 - __bfloat162float(h0)),
                    __float2bfloat16(v1 - __bfloat162float(h1)));
            }
        }
}

// v projection. grid (64, 4): slabs 0..3 -> fp32 g_v.
__global__ void __launch_bounds__(256, 2) gemm_v()
{
    extern __shared__ char smem[];
    const int slab = blockIdx.y * 128;
    const int m0 = blockIdx.x * 64;

    float acc[2][4][4] = {};
    mainloop64(g_xh, g_xl,
               g_wh + 2ull * NN + (size_t)slab * 512,
               g_wl + 2ull * NN + (size_t)slab * 512,
               m0, smem, acc);

    const int tid = threadIdx.x, lane = tid & 31;
    const int wid = tid >> 5;
    const int wm = wid & 1, wn = wid >> 1;
    const int r0 = m0 + wm * 32 + (lane >> 2);
    const int c0 = slab + wn * 32 + (lane & 3) * 2;
#pragma unroll
    for (int f = 0; f < 2; ++f)
#pragma unroll
        for (int n = 0; n < 4; ++n) {
            float* p0 = g_v + (size_t)(r0 + f * 16) * 512 + c0 + n * 8;
            *(float2*)p0 = make_float2(acc[f][n][0], acc[f][n][1]);
            *(float2*)(p0 + 8 * 512) = make_float2(acc[f][n][2], acc[f][n][3]);
        }
}

// Output projection: out = a @ wo^T. grid (64, 4).
__global__ void __launch_bounds__(256, 2) gemm_out(float* __restrict__ out)
{
    extern __shared__ char smem[];
    const int brow = blockIdx.y * 128;
    const int m0 = blockIdx.x * 64;
    float acc[2][4][4] = {};
    mainloop64(g_ah, g_al,
               g_wh + 3ull * NN + (size_t)brow * 512,
               g_wl + 3ull * NN + (size_t)brow * 512,
               m0, smem, acc);
    const int tid = threadIdx.x, lane = tid & 31;
    const int wid = tid >> 5;
    const int wm = wid & 1, wn = wid >> 1;
    const int r0 = m0 + wm * 32 + (lane >> 2);
    const int c0 = brow + wn * 32 + (lane & 3) * 2;
#pragma unroll
    for (int f = 0; f < 2; ++f)
#pragma unroll
        for (int n = 0; n < 4; ++n) {
            float* p0 = out + (size_t)(r0 + f * 16) * 512 + c0 + n * 8;
            *(float2*)p0 = make_float2(acc[f][n][0], acc[f][n][1]);
            *(float2*)(p0 + 8 * 512) = make_float2(acc[f][n][2], acc[f][n][3]);
        }
}

// ================= gemm_w via MMA: w1 = q.sk^T, w2t = k.sq^T ======================
#define GW_SMEM (2*49152)
__global__ void __launch_bounds__(256, 2) gemm_w_mma()
{
    extern __shared__ char smem[];
    const uint32_t sb = smem_u32(smem);
    const int tid = threadIdx.x, lane = tid & 31;
    const int wm = (tid >> 5) & 3, wn = tid >> 7;
    const int second = blockIdx.z;
    const int bh_ = blockIdx.y;
    const int b = bh_ / 3, hm = bh_ % 3;
    const int m0 = blockIdx.x * 128;

    const __nv_bfloat16* Ah = (second ? g_kh : g_qh) + (size_t)b*Tv*QKW + hm*HDv;
    const __nv_bfloat16* Al = (second ? g_kl : g_ql) + (size_t)b*Tv*QKW + hm*HDv;
    const __nv_bfloat16* Bh = (second ? g_sqh : g_skh) + (size_t)bh_*Lv*HDv;
    const __nv_bfloat16* Bl = (second ? g_sql : g_skl) + (size_t)bh_*Lv*HDv;
    float* C = (second ? g_w2t : g_w1) + ((size_t)((b*4+hm+1)*Tv) + m0) * Lv;

    float acc[2][4][4] = {};

    auto load_stage = [&](int kc, uint32_t dstb) {
#pragma unroll
        for (int t = 0; t < 2; ++t) {
            const __nv_bfloat16* base = t ? Al : Ah;
#pragma unroll
            for (int j = 0; j < 4; ++j) {
                int idx = j * 256 + tid;
                int row = idx >> 3, c = idx & 7;
                CP16(dstb + t * 16384 + sw128((uint32_t)(row * 128 + c * 16)),
                     base + (size_t)(m0 + row) * QKW + kc * 64 + c * 8);
            }
        }
#pragma unroll
        for (int t = 0; t < 2; ++t) {
            const __nv_bfloat16* base = t ? Bl : Bh;
#pragma unroll
            for (int j = 0; j < 2; ++j) {
                int idx = j * 256 + tid;
                int row = idx >> 3, c = idx & 7;
                CP16(dstb + 32768 + t * 8192 + sw128((uint32_t)(row * 128 + c * 16)),
                     base + (size_t)row * HDv + kc * 64 + c * 8);
            }
        }
    };

    load_stage(0, sb); CP_COMMIT();
    load_stage(1, sb + 49152); CP_COMMIT();

    for (int kc = 0; kc < 2; ++kc) {
        if (kc == 0) asm volatile("cp.async.wait_group 1;" ::: "memory");
        else         asm volatile("cp.async.wait_group 0;" ::: "memory");
        __syncthreads();
        const uint32_t sbuf = sb + kc * 49152;
#pragma unroll
        for (int kk = 0; kk < 4; ++kk) {
            const int klo = kk * 2;
            uint32_t ah[2][4], al[2][4], bh[4][2], bl[4][2];
            const int arow = ((lane >> 3) & 1) * 8 + (lane & 7);
            const int achk = klo + (lane >> 4);
#pragma unroll
            for (int f = 0; f < 2; ++f) {
                uint32_t off = sw128((uint32_t)((wm * 32 + f * 16 + arow) * 128 + achk * 16));
                LDSM4(ah[f], sbuf + off);
                LDSM4(al[f], sbuf + 16384 + off);
            }
            const int brow = (lane >> 4) * 8 + (lane & 7);
            const int bchk = klo + ((lane >> 3) & 1);
#pragma unroll
            for (int p = 0; p < 2; ++p) {
                uint32_t off = sw128((uint32_t)((wn * 32 + p * 16 + brow) * 128 + bchk * 16));
                uint32_t r[4];
                LDSM4(r, sbuf + 32768 + off);
                bh[2*p][0] = r[0]; bh[2*p][1] = r[1];
                bh[2*p+1][0] = r[2]; bh[2*p+1][1] = r[3];
                LDSM4(r, sbuf + 40960 + off);
                bl[2*p][0] = r[0]; bl[2*p][1] = r[1];
                bl[2*p+1][0] = r[2]; bl[2*p+1][1] = r[3];
            }
#pragma unroll
            for (int f = 0; f < 2; ++f)
#pragma unroll
                for (int n = 0; n < 4; ++n) {
                    MMA16816(acc[f][n], ah[f], bh[n]);
                    MMA16816(acc[f][n], ah[f], bl[n]);
                    MMA16816(acc[f][n], al[f], bh[n]);
                }
        }
        __syncthreads();
    }

    const int r0 = wm * 32 + (lane >> 2);
    const int c0 = wn * 32 + (lane & 3) * 2;
#pragma unroll
    for (int f = 0; f < 2; ++f)
#pragma unroll
        for (int n = 0; n < 4; ++n) {
            float* p0 = C + (size_t)(r0 + f * 16) * Lv + c0 + n * 8;
            *(float2*)p0 = make_float2(acc[f][n][0], acc[f][n][1]);
            *(float2*)(p0 + 8 * Lv) = make_float2(acc[f][n][2], acc[f][n][3]);
        }
}

// ================= fused fp32 -> (hi,lo) bf16 split (x + 4 weights) =================
__global__ void split_all(const float2* __restrict__ x,
                          const float2* __restrict__ w0, const float2* __restrict__ w1,
                          const float2* __restrict__ w2, const float2* __restrict__ w3)
{
    int bid = blockIdx.x;
    const float2* src;
    __nv_bfloat162 *dh, *dl;
    size_t i;
    if (bid < 4096) {
        i = (size_t)bid * 256 + threadIdx.x;
        src = x; dh = (__nv_bfloat162*)g_xh; dl = (__nv_bfloat162*)g_xl;
    } else {
        int r = bid - 4096;
        int widx = r >> 9;
        i = (size_t)(r & 511) * 256 + threadIdx.x;
        src = (widx == 0) ? w0 : (widx == 1) ? w1 : (widx == 2) ? w2 : w3;
        dh = (__nv_bfloat162*)g_wh + (size_t)widx * (NN/2);
        dl = (__nv_bfloat162*)g_wl + (size_t)widx * (NN/2);
    }
    float2 v = src[i];
    __nv_bfloat16 h0 = __float2bfloat16(v.x);
    __nv_bfloat16 h1 = __float2bfloat16(v.y);
    dh[i] = __halves2bfloat162(h0, h1);
    dl[i] = __halves2bfloat162(__float2bfloat16(v.x - __bfloat162float(h0)),
                               __float2bfloat16(v.y - __bfloat162float(h1)));
}

// ================= lam scalar =================
__global__ void lam_kernel(const float* __restrict__ lq1, const float* __restrict__ lk1,
                           const float* __restrict__ lq2, const float* __restrict__ lk2,
                           const int* __restrict__ lptr)
{
    __shared__ float r1[128], r2[128];
    int t = threadIdx.x;
    r1[t] = lq1[t]*lk1[t];
    r2[t] = lq2[t]*lk2[t];
    __syncthreads();
    for (int o = 64; o; o >>= 1) {
        if (t < o) { r1[t] += r1[t+o]; r2[t] += r2[t+o]; }
        __syncthreads();
    }
    if (t == 0) {
        float lam_init = 0.8f - 0.6f*expf(-0.3f*(float)lptr[0]);
        g_scal[0] = expf(r1[0]) - expf(r2[0]) + lam_init;
        g_scal[1] = 1.0f - lam_init;
    }
}

// ================= sq / sk: warp-per-task reconstruct+normalize+scale+split ========
__global__ void __launch_bounds__(256) sqsk_kernel(const int* __restrict__ landmark,
                                                   const float* __restrict__ m1,
                                                   const float* __restrict__ m2)
{
    int task = blockIdx.x * 8 + (threadIdx.x >> 5);
    int lane = threadIdx.x & 31;
    int which = task & 1;
    int rest = task >> 1;
    int j  = rest & 63;
    int hm = (rest >> 6) % 3;
    int b  = rest / 192;
    int tok = landmark[j];

    size_t off = (size_t)(b*Tv + tok)*QKW + hm*HDv + lane*4;
    const __nv_bfloat16* ph = which ? g_kh : g_qh;
    const __nv_bfloat16* pl = which ? g_kl : g_ql;
    float v[4];
#pragma unroll
    for (int e = 0; e < 4; ++e)
        v[e] = __bfloat162float(ph[off+e]) + __bfloat162float(pl[off+e]);

    float ss = v[0]*v[0] + v[1]*v[1] + v[2]*v[2] + v[3]*v[3];
#pragma unroll
    for (int o = 16; o; o >>= 1) ss += __shfl_xor_sync(0xffffffffu, ss, o);

    float scale = (which ? m2[(hm+1)*Lv + j] : m1[(hm+1)*Lv + j]) * rsqrtf(ss);
    __nv_bfloat16* dh = which ? g_skh : g_sqh;
    __nv_bfloat16* dl = which ? g_skl : g_sql;
    size_t d = ((size_t)(b*3 + hm)*Lv + j)*HDv + lane*4;
#pragma unroll
    for (int e = 0; e < 4; ++e) {
        float o = v[e] * scale;
        __nv_bfloat16 h = __float2bfloat16(o);
        dh[d+e] = h;
        dl[d+e] = __float2bfloat16(o - __bfloat162float(h));
    }
}

// ================= symmetric mask -> per-row CSR =================
__global__ void mask_kernel(const int* __restrict__ rns)
{
    int warp = (blockIdx.x * blockDim.x + threadIdx.x) >> 5;
    int lane = threadIdx.x & 31;
    int b = warp >> 11, i = warp & (Tv-1);
    const int* row = rns + (size_t)warp * KIv;
    int j = row[lane];
    bool dup = false;
#pragma unroll
    for (int k2 = 0; k2 < 32; ++k2) {
        int jj = __shfl_sync(0xffffffffu, j, k2);
        if (k2 < lane && jj == j) dup = true;
    }
    bool mem = false;
    const int* rj = rns + (size_t)(b*Tv + j)*KIv;
#pragma unroll
    for (int m = 0; m < 32; ++m) if (rj[m] == i) mem = true;
    bool valid = (!dup) && mem;
    unsigned bal = __ballot_sync(0xffffffffu, valid);
    if (valid) {
        int pos = __popc(bal & ((1u << lane) - 1u));
        g_cols[(size_t)warp*KIv + pos] = j;
    }
    if (lane == 0) g_cnt[warp] = __popc(bal);
}

// ================= column partial sums of v (zero-nnz rows) =================
__global__ void colsumA()
{
    int g = blockIdx.x*256 + threadIdx.x;
    int chunk = g >> 10;
    int c = g & 1023;
    int b = c >> 9, col = c & 511;
    const float* p = g_v + (size_t)(b*Tv + chunk*256)*NXv + col;
    float s = 0.f;
    for (int t = 0; t < 256; ++t) s += p[(size_t)t*NXv];
    g_vpart[g] = s;
}

// ================= sparse attention rows + wmix + RMSNorm + bf16 split ===========
__global__ void __launch_bounds__(256) attn_rows(const float* __restrict__ rms_g)
{
    const int r = blockIdx.x;
    const int b = r >> 11;
    const int i = r & (Tv-1);
    const int tid = threadIdx.x;
    __shared__ int   scols[KIv];
    __shared__ float sw[3][KIv];
    __shared__ float c0[KIv], c1[KIv];
    __shared__ float red[512];
    const int cnt = g_cnt[r];
    if (tid < KIv && tid < cnt) scols[tid] = g_cols[(size_t)r*KIv + tid];
    __syncthreads();
    const float lam = g_scal[0];
    const int wid = tid >> 5, lane = tid & 31;

    for (int task = wid; task < 3*cnt; task += 8) {
        int hm = task % 3, j = task / 3, h = hm + 1;
        const float* w1p = g_w1  + ((size_t)((b*4+h)*Tv + i)        << 6);
        const float* w2p = g_w2t + ((size_t)((b*4+h)*Tv + scols[j]) << 6);
        float s = w1p[lane]*w2p[lane] + w1p[lane+32]*w2p[lane+32];
#pragma unroll
        for (int o = 16; o; o >>= 1) s += __shfl_xor_sync(0xffffffffu, s, o);
        if (lane == 0) sw[hm][j] = s;
    }
    __syncthreads();

    if (wid == 0 && cnt > 0) {
        float p[3];
#pragma unroll
        for (int hm = 0; hm < 3; ++hm) {
            float x = (lane < cnt) ? sw[hm][lane] : -INFINITY;
            float mx = x;
#pragma unroll
            for (int o = 16; o; o >>= 1) mx = fmaxf(mx, __shfl_xor_sync(0xffffffffu, mx, o));
            float e = (lane < cnt) ? expf(x - mx) : 0.f;
            float sm = e;
#pragma unroll
            for (int o = 16; o; o >>= 1) sm += __shfl_xor_sync(0xffffffffu, sm, o);
            p[hm] = e / sm;
        }
        if (lane < cnt) {
            c0[lane] = (1.f - lam)*p[1] - lam*p[0];
            c1[lane] = p[1] - p[0] + (1.f - 2.f*lam)*p[2];
        }
    }
    __syncthreads();

    float s0 = 0.f, s1 = 0.f;
    if (cnt > 0) {
#pragma unroll 4
        for (int j = 0; j < cnt; ++j) {
            const float* vp = g_v + ((size_t)(b*Tv + scols[j]) << 9);
            s0 += c0[j] * vp[tid];
            s1 += c1[j] * vp[tid + 256];
        }
    } else {
        float u = (1.f - 2.f*lam) * (1.f/(float)Tv);
        float t0 = 0.f, t1 = 0.f;
#pragma unroll
        for (int ch = 0; ch < 8; ++ch) {
            t0 += g_vpart[ch*1024 + b*512 + tid];
            t1 += g_vpart[ch*1024 + b*512 + tid + 256];
        }
        s0 = u * t0;
        s1 = u * t1;
    }

    red[tid]       = s0*s0;
    red[tid + 256] = s1*s1;
    __syncthreads();
#pragma unroll
    for (int o = 128; o; o >>= 1) {
        if (tid < o) { red[tid] += red[tid+o]; red[256+tid] += red[256+tid+o]; }
        __syncthreads();
    }
    float onem = g_scal[1];
    float g = rms_g[tid];
    float a0 = s0 * rsqrtf(red[0]  *(1.f/256.f) + 1e-5f) * g * onem;
    float a1 = s1 * rsqrtf(red[256]*(1.f/256.f) + 1e-5f) * g * onem;
    __nv_bfloat16 h0 = __float2bfloat16(a0);
    __nv_bfloat16 h1 = __float2bfloat16(a1);
    size_t o0 = (size_t)r*NXv + tid, o1 = o0 + 256;
    g_ah[o0] = h0;                                   g_ah[o1] = h1;
    g_al[o0] = __float2bfloat16(a0 - __bfloat162float(h0));
    g_al[o1] = __float2bfloat16(a1 - __bfloat162float(h1));
}

// ================= launch (multi-stream fork/join, graph-capture safe) =============
extern "C" void kernel_launch(void* const* d_in, const int* in_sizes, int n_in,
                              void* d_out, int out_size)
{
    const float* x    = (const float*)d_in[0];
    const float* wq   = (const float*)d_in[1];
    const float* wk   = (const float*)d_in[2];
    const float* wv   = (const float*)d_in[3];
    const float* wo   = (const float*)d_in[4];
    const float* m1   = (const float*)d_in[5];
    const float* m2   = (const float*)d_in[6];
    const float* lq1  = (const float*)d_in[7];
    const float* lk1  = (const float*)d_in[8];
    const float* lq2  = (const float*)d_in[9];
    const float* lk2  = (const float*)d_in[10];
    const float* rmsg = (const float*)d_in[11];
    const int*   lp   = (const int*)d_in[12];
    const int*   rns  = (const int*)d_in[14];
    const int*   lmk  = (const int*)d_in[15];
    float* out = (float*)d_out;

    static cudaStream_t s1 = nullptr, s2 = nullptr;
    static cudaEvent_t e_fork = nullptr, e_mask = nullptr, e_split = nullptr, e_cols = nullptr;
    static int inited = 0;
    if (!inited) {
        cudaStreamCreateWithFlags(&s1, cudaStreamNonBlocking);
        cudaStreamCreateWithFlags(&s2, cudaStreamNonBlocking);
        cudaEventCreateWithFlags(&e_fork,  cudaEventDisableTiming);
        cudaEventCreateWithFlags(&e_mask,  cudaEventDisableTiming);
        cudaEventCreateWithFlags(&e_split, cudaEventDisableTiming);
        cudaEventCreateWithFlags(&e_cols,  cudaEventDisableTiming);
        cudaFuncSetAttribute(gemm_qk,    cudaFuncAttributeMaxDynamicSharedMemorySize, GEMM_SMEM_TOTAL);
        cudaFuncSetAttribute(gemm_v,     cudaFuncAttributeMaxDynamicSharedMemorySize, GEMM_SMEM_TOTAL);
        cudaFuncSetAttribute(gemm_out,   cudaFuncAttributeMaxDynamicSharedMemorySize, GEMM_SMEM_TOTAL);
        cudaFuncSetAttribute(gemm_w_mma, cudaFuncAttributeMaxDynamicSharedMemorySize, GW_SMEM);
        inited = 1;
    }

    // fork: lam + mask depend only on kernel inputs -> run on s1 concurrently
    cudaEventRecord(e_fork, 0);
    cudaStreamWaitEvent(s1, e_fork, 0);
    lam_kernel<<<1, 128, 0, s1>>>(lq1, lk1, lq2, lk2, lp);
    mask_kernel<<<Bv*Tv*32/256, 256, 0, s1>>>(rns);
    cudaEventRecord(e_mask, s1);

    // main chain: split, then qk on main / v on s2 concurrently
    split_all<<<6144, 256>>>((const float2*)x, (const float2*)wq, (const float2*)wk,
                             (const float2*)wv, (const float2*)wo);
    cudaEventRecord(e_split, 0);

    cudaStreamWaitEvent(s2, e_split, 0);
    gemm_v<<<dim3(Bv*Tv/64, 4), 256, GEMM_SMEM_TOTAL, s2>>>();
    colsumA<<<32, 256, 0, s2>>>();
    cudaEventRecord(e_cols, s2);

    gemm_qk<<<dim3(Bv*Tv/64, 6), 256, GEMM_SMEM_TOTAL>>>();
    sqsk_kernel<<<96, 256>>>(lmk, m1, m2);
    gemm_w_mma<<<dim3(Tv/128, Bv*3, 2), 256, GW_SMEM>>>();

    // join: attn_rows needs mask (s1), v+colsum (s2), w1/w2 (main)
    cudaStreamWaitEvent(0, e_mask, 0);
    cudaStreamWaitEvent(0, e_cols, 0);
    attn_rows<<<Bv*Tv, 256>>>(rmsg);
    gemm_out<<<dim3(Bv*Tv/64, 4), 256, GEMM_SMEM_TOTAL>>>(out);
}

// round 11
// speedup vs baseline: 1.1296x; 1.0113x over previous
#include <cuda_runtime.h>
#include <cuda_bf16.h>
#include <math.h>
#include <cstdint>

#define Bv 2
#define Tv 2048
#define NXv 512
#define HDv 128
#define Lv 64
#define KIv 32
#define NN (NXv*NXv)
#define QKW 384   // pruned q/k width (heads 1..3)

// ================= scratch (device globals; no allocation allowed) =================
__device__ float g_v[Bv*Tv*NXv];
__device__ float g_w1 [Bv*4*Tv*Lv];
__device__ float g_w2t[Bv*4*Tv*Lv];
__device__ int   g_cols[Bv*Tv*KIv];
__device__ int   g_cnt [Bv*Tv];
__device__ float g_vpart[8*Bv*NXv];
__device__ float g_scal[2];
__device__ __nv_bfloat16 g_xh[Bv*Tv*NXv], g_xl[Bv*Tv*NXv];
__device__ __nv_bfloat16 g_ah[Bv*Tv*NXv], g_al[Bv*Tv*NXv];
__device__ __nv_bfloat16 g_wh[4*NN], g_wl[4*NN];
__device__ __nv_bfloat16 g_qh[Bv*Tv*QKW], g_ql[Bv*Tv*QKW];
__device__ __nv_bfloat16 g_kh[Bv*Tv*QKW], g_kl[Bv*Tv*QKW];
__device__ __nv_bfloat16 g_skh[Bv*3*Lv*HDv], g_skl[Bv*3*Lv*HDv];
__device__ __nv_bfloat16 g_sqh[Bv*3*Lv*HDv], g_sql[Bv*3*Lv*HDv];

// ================= helpers =================
__device__ __forceinline__ uint32_t smem_u32(const void* p) {
    uint32_t a;
    asm("{ .reg .u64 t; cvta.to.shared.u64 t, %1; cvt.u32.u64 %0, t; }" : "=r"(a) : "l"(p));
    return a;
}
__device__ __forceinline__ uint32_t sw128(uint32_t off) { return off ^ ((off >> 3) & 0x70); }

#define CP16(dst, src)  asm volatile("cp.async.cg.shared.global [%0], [%1], 16;" :: "r"(dst), "l"(src) : "memory")
#define CP_COMMIT()     asm volatile("cp.async.commit_group;" ::: "memory")

#define LDSM4(r, a) \
    asm volatile("ldmatrix.sync.aligned.m8n8.x4.shared.b16 {%0,%1,%2,%3}, [%4];" \
        : "=r"((r)[0]), "=r"((r)[1]), "=r"((r)[2]), "=r"((r)[3]) : "r"(a))

#define MMA16816(d, a, b) \
    asm volatile("mma.sync.aligned.m16n8k16.row.col.f32.bf16.bf16.f32 " \
        "{%0,%1,%2,%3},{%4,%5,%6,%7},{%8,%9},{%0,%1,%2,%3};" \
        : "+f"((d)[0]), "+f"((d)[1]), "+f"((d)[2]), "+f"((d)[3]) \
        : "r"((a)[0]), "r"((a)[1]), "r"((a)[2]), "r"((a)[3]), "r"((b)[0]), "r"((b)[1]))

// ================= 256-thread split-bf16 MMA mainloop: 64x128 tile, K=512 ==========
#define STAGE_BYTES 49152
#define GEMM_SMEM_TOTAL (2*STAGE_BYTES)

__device__ __forceinline__ void mainloop64(
    const __nv_bfloat16* __restrict__ Ah, const __nv_bfloat16* __restrict__ Al,
    const __nv_bfloat16* __restrict__ Bh, const __nv_bfloat16* __restrict__ Bl,
    int m0, char* smem, float acc[2][4][4])
{
    const uint32_t sb = smem_u32(smem);
    const int tid = threadIdx.x, lane = tid & 31;
    const int wid = tid >> 5;
    const int wm = wid & 1, wn = wid >> 1;

    auto load_stage = [&](int kc, uint32_t dstb) {
#pragma unroll
        for (int t = 0; t < 2; ++t) {
            const __nv_bfloat16* base = t ? Al : Ah;
#pragma unroll
            for (int j = 0; j < 2; ++j) {
                int idx = j * 256 + tid;
                int row = idx >> 3, c = idx & 7;
                CP16(dstb + t * 8192 + sw128((uint32_t)(row * 128 + c * 16)),
                     base + (size_t)(m0 + row) * 512 + kc * 64 + c * 8);
            }
        }
#pragma unroll
        for (int t = 0; t < 2; ++t) {
            const __nv_bfloat16* base = t ? Bl : Bh;
#pragma unroll
            for (int j = 0; j < 4; ++j) {
                int idx = j * 256 + tid;
                int row = idx >> 3, c = idx & 7;
                CP16(dstb + 16384 + t * 16384 + sw128((uint32_t)(row * 128 + c * 16)),
                     base + (size_t)row * 512 + kc * 64 + c * 8);
            }
        }
    };

    load_stage(0, sb);
    CP_COMMIT();

    for (int kc = 0; kc < 8; ++kc) {
        if (kc < 7) {
            load_stage(kc + 1, sb + ((kc + 1) & 1) * STAGE_BYTES);
            CP_COMMIT();
            asm volatile("cp.async.wait_group 1;" ::: "memory");
        } else {
            asm volatile("cp.async.wait_group 0;" ::: "memory");
        }
        __syncthreads();
        const uint32_t sbuf = sb + (kc & 1) * STAGE_BYTES;

#pragma unroll
        for (int kk = 0; kk < 4; ++kk) {
            const int klo = kk * 2;
            uint32_t ah[2][4], al[2][4], bh[4][2], bl[4][2];
            const int arow = ((lane >> 3) & 1) * 8 + (lane & 7);
            const int achk = klo + (lane >> 4);
#pragma unroll
            for (int f = 0; f < 2; ++f) {
                uint32_t off = sw128((uint32_t)((wm * 32 + f * 16 + arow) * 128 + achk * 16));
                LDSM4(ah[f], sbuf + off);
                LDSM4(al[f], sbuf + 8192 + off);
            }
            const int brow = (lane >> 4) * 8 + (lane & 7);
            const int bchk = klo + ((lane >> 3) & 1);
#pragma unroll
            for (int p = 0; p < 2; ++p) {
                uint32_t off = sw128((uint32_t)((wn * 32 + p * 16 + brow) * 128 + bchk * 16));
                uint32_t r[4];
                LDSM4(r, sbuf + 16384 + off);
                bh[2*p][0] = r[0]; bh[2*p][1] = r[1];
                bh[2*p+1][0] = r[2]; bh[2*p+1][1] = r[3];
                LDSM4(r, sbuf + 32768 + off);
                bl[2*p][0] = r[0]; bl[2*p][1] = r[1];
                bl[2*p+1][0] = r[2]; bl[2*p+1][1] = r[3];
            }
#pragma unroll
            for (int f = 0; f < 2; ++f)
#pragma unroll
                for (int n = 0; n < 4; ++n) {
                    MMA16816(acc[f][n], ah[f], bh[n]);
                    MMA16816(acc[f][n], ah[f], bl[n]);
                    MMA16816(acc[f][n], al[f], bh[n]);
                }
        }
        __syncthreads();
    }
}

// q/k projection. grid (64, 6): y 0..2 q slabs 128.., y 3..5 k slabs 128..
__global__ void __launch_bounds__(256, 2) gemm_qk()
{
    extern __shared__ char smem[];
    const int y = blockIdx.y;
    const int widx = (y < 3) ? 0 : 1;
    const int slab = 128 + (y % 3) * 128;
    const int m0 = blockIdx.x * 64;

    float acc[2][4][4] = {};
    mainloop64(g_xh, g_xl,
               g_wh + (size_t)widx * NN + (size_t)slab * 512,
               g_wl + (size_t)widx * NN + (size_t)slab * 512,
               m0, smem, acc);

    const int tid = threadIdx.x, lane = tid & 31;
    const int wid = tid >> 5;
    const int wm = wid & 1, wn = wid >> 1;
    const int r0 = m0 + wm * 32 + (lane >> 2);
    const int c0 = wn * 32 + (lane & 3) * 2;

    __nv_bfloat16* dh = widx ? g_kh : g_qh;
    __nv_bfloat16* dl = widx ? g_kl : g_ql;
    const int cp0 = (slab - 128) + c0;
#pragma unroll
    for (int f = 0; f < 2; ++f)
#pragma unroll
        for (int n = 0; n < 4; ++n) {
#pragma unroll
            for (int hr = 0; hr < 2; ++hr) {
                const int row = r0 + f * 16 + hr * 8;
                float v0 = acc[f][n][hr*2], v1 = acc[f][n][hr*2+1];
                __nv_bfloat16 h0 = __float2bfloat16(v0), h1 = __float2bfloat16(v1);
                size_t o = (size_t)row * QKW + cp0 + n * 8;
                *(__nv_bfloat162*)(dh + o) = __halves2bfloat162(h0, h1);
                *(__nv_bfloat162*)(dl + o) = __halves2bfloat162(
                    __float2bfloat16(v0 - __bfloat162float(h0)),
                    __float2bfloat16(v1 - __bfloat162float(h1)));
            }
        }
}

// v projection. grid (64, 4): slabs 0..3 -> fp32 g_v.
__global__ void __launch_bounds__(256, 2) gemm_v()
{
    extern __shared__ char smem[];
    const int slab = blockIdx.y * 128;
    const int m0 = blockIdx.x * 64;

    float acc[2][4][4] = {};
    mainloop64(g_xh, g_xl,
               g_wh + 2ull * NN + (size_t)slab * 512,
               g_wl + 2ull * NN + (size_t)slab * 512,
               m0, smem, acc);

    const int tid = threadIdx.x, lane = tid & 31;
    const int wid = tid >> 5;
    const int wm = wid & 1, wn = wid >> 1;
    const int r0 = m0 + wm * 32 + (lane >> 2);
    const int c0 = slab + wn * 32 + (lane & 3) * 2;
#pragma unroll
    for (int f = 0; f < 2; ++f)
#pragma unroll
        for (int n = 0; n < 4; ++n) {
            float* p0 = g_v + (size_t)(r0 + f * 16) * 512 + c0 + n * 8;
            *(float2*)p0 = make_float2(acc[f][n][0], acc[f][n][1]);
            *(float2*)(p0 + 8 * 512) = make_float2(acc[f][n][2], acc[f][n][3]);
        }
}

// Output projection: out = a @ wo^T. grid (32, 4), m window via m_base.
__global__ void __launch_bounds__(256, 2) gemm_out(float* __restrict__ out, int m_base)
{
    extern __shared__ char smem[];
    const int brow = blockIdx.y * 128;
    const int m0 = m_base + blockIdx.x * 64;
    float acc[2][4][4] = {};
    mainloop64(g_ah, g_al,
               g_wh + 3ull * NN + (size_t)brow * 512,
               g_wl + 3ull * NN + (size_t)brow * 512,
               m0, smem, acc);
    const int tid = threadIdx.x, lane = tid & 31;
    const int wid = tid >> 5;
    const int wm = wid & 1, wn = wid >> 1;
    const int r0 = m0 + wm * 32 + (lane >> 2);
    const int c0 = brow + wn * 32 + (lane & 3) * 2;
#pragma unroll
    for (int f = 0; f < 2; ++f)
#pragma unroll
        for (int n = 0; n < 4; ++n) {
            float* p0 = out + (size_t)(r0 + f * 16) * 512 + c0 + n * 8;
            *(float2*)p0 = make_float2(acc[f][n][0], acc[f][n][1]);
            *(float2*)(p0 + 8 * 512) = make_float2(acc[f][n][2], acc[f][n][3]);
        }
}

// ================= gemm_w via MMA: w1 = q.sk^T, w2t = k.sq^T ======================
#define GW_SMEM (2*49152)
__global__ void __launch_bounds__(256, 2) gemm_w_mma()
{
    extern __shared__ char smem[];
    const uint32_t sb = smem_u32(smem);
    const int tid = threadIdx.x, lane = tid & 31;
    const int wm = (tid >> 5) & 3, wn = tid >> 7;
    const int second = blockIdx.z;
    const int bh_ = blockIdx.y;
    const int b = bh_ / 3, hm = bh_ % 3;
    const int m0 = blockIdx.x * 128;

    const __nv_bfloat16* Ah = (second ? g_kh : g_qh) + (size_t)b*Tv*QKW + hm*HDv;
    const __nv_bfloat16* Al = (second ? g_kl : g_ql) + (size_t)b*Tv*QKW + hm*HDv;
    const __nv_bfloat16* Bh = (second ? g_sqh : g_skh) + (size_t)bh_*Lv*HDv;
    const __nv_bfloat16* Bl = (second ? g_sql : g_skl) + (size_t)bh_*Lv*HDv;
    float* C = (second ? g_w2t : g_w1) + ((size_t)((b*4+hm+1)*Tv) + m0) * Lv;

    float acc[2][4][4] = {};

    auto load_stage = [&](int kc, uint32_t dstb) {
#pragma unroll
        for (int t = 0; t < 2; ++t) {
            const __nv_bfloat16* base = t ? Al : Ah;
#pragma unroll
            for (int j = 0; j < 4; ++j) {
                int idx = j * 256 + tid;
                int row = idx >> 3, c = idx & 7;
                CP16(dstb + t * 16384 + sw128((uint32_t)(row * 128 + c * 16)),
                     base + (size_t)(m0 + row) * QKW + kc * 64 + c * 8);
            }
        }
#pragma unroll
        for (int t = 0; t < 2; ++t) {
            const __nv_bfloat16* base = t ? Bl : Bh;
#pragma unroll
            for (int j = 0; j < 2; ++j) {
                int idx = j * 256 + tid;
                int row = idx >> 3, c = idx & 7;
                CP16(dstb + 32768 + t * 8192 + sw128((uint32_t)(row * 128 + c * 16)),
                     base + (size_t)row * HDv + kc * 64 + c * 8);
            }
        }
    };

    load_stage(0, sb); CP_COMMIT();
    load_stage(1, sb + 49152); CP_COMMIT();

    for (int kc = 0; kc < 2; ++kc) {
        if (kc == 0) asm volatile("cp.async.wait_group 1;" ::: "memory");
        else         asm volatile("cp.async.wait_group 0;" ::: "memory");
        __syncthreads();
        const uint32_t sbuf = sb + kc * 49152;
#pragma unroll
        for (int kk = 0; kk < 4; ++kk) {
            const int klo = kk * 2;
            uint32_t ah[2][4], al[2][4], bh[4][2], bl[4][2];
            const int arow = ((lane >> 3) & 1) * 8 + (lane & 7);
            const int achk = klo + (lane >> 4);
#pragma unroll
            for (int f = 0; f < 2; ++f) {
                uint32_t off = sw128((uint32_t)((wm * 32 + f * 16 + arow) * 128 + achk * 16));
                LDSM4(ah[f], sbuf + off);
                LDSM4(al[f], sbuf + 16384 + off);
            }
            const int brow = (lane >> 4) * 8 + (lane & 7);
            const int bchk = klo + ((lane >> 3) & 1);
#pragma unroll
            for (int p = 0; p < 2; ++p) {
                uint32_t off = sw128((uint32_t)((wn * 32 + p * 16 + brow) * 128 + bchk * 16));
                uint32_t r[4];
                LDSM4(r, sbuf + 32768 + off);
                bh[2*p][0] = r[0]; bh[2*p][1] = r[1];
                bh[2*p+1][0] = r[2]; bh[2*p+1][1] = r[3];
                LDSM4(r, sbuf + 40960 + off);
                bl[2*p][0] = r[0]; bl[2*p][1] = r[1];
                bl[2*p+1][0] = r[2]; bl[2*p+1][1] = r[3];
            }
#pragma unroll
            for (int f = 0; f < 2; ++f)
#pragma unroll
                for (int n = 0; n < 4; ++n) {
                    MMA16816(acc[f][n], ah[f], bh[n]);
                    MMA16816(acc[f][n], ah[f], bl[n]);
                    MMA16816(acc[f][n], al[f], bh[n]);
                }
        }
        __syncthreads();
    }

    const int r0 = wm * 32 + (lane >> 2);
    const int c0 = wn * 32 + (lane & 3) * 2;
#pragma unroll
    for (int f = 0; f < 2; ++f)
#pragma unroll
        for (int n = 0; n < 4; ++n) {
            float* p0 = C + (size_t)(r0 + f * 16) * Lv + c0 + n * 8;
            *(float2*)p0 = make_float2(acc[f][n][0], acc[f][n][1]);
            *(float2*)(p0 + 8 * Lv) = make_float2(acc[f][n][2], acc[f][n][3]);
        }
}

// ================= fp32 -> (hi,lo) bf16 splits =================
__global__ void split_x(const float2* __restrict__ x)
{
    size_t i = (size_t)blockIdx.x * 256 + threadIdx.x;
    float2 v = x[i];
    __nv_bfloat16 h0 = __float2bfloat16(v.x);
    __nv_bfloat16 h1 = __float2bfloat16(v.y);
    ((__nv_bfloat162*)g_xh)[i] = __halves2bfloat162(h0, h1);
    ((__nv_bfloat162*)g_xl)[i] = __halves2bfloat162(
        __float2bfloat16(v.x - __bfloat162float(h0)),
        __float2bfloat16(v.y - __bfloat162float(h1)));
}
__global__ void split_w(const float2* __restrict__ w0, const float2* __restrict__ w1,
                        const float2* __restrict__ w2, const float2* __restrict__ w3)
{
    int widx = blockIdx.x >> 9;
    size_t i = (size_t)(blockIdx.x & 511) * 256 + threadIdx.x;
    const float2* src = (widx == 0) ? w0 : (widx == 1) ? w1 : (widx == 2) ? w2 : w3;
    __nv_bfloat162* dh = (__nv_bfloat162*)g_wh + (size_t)widx * (NN/2);
    __nv_bfloat162* dl = (__nv_bfloat162*)g_wl + (size_t)widx * (NN/2);
    float2 v = src[i];
    __nv_bfloat16 h0 = __float2bfloat16(v.x);
    __nv_bfloat16 h1 = __float2bfloat16(v.y);
    dh[i] = __halves2bfloat162(h0, h1);
    dl[i] = __halves2bfloat162(__float2bfloat16(v.x - __bfloat162float(h0)),
                               __float2bfloat16(v.y - __bfloat162float(h1)));
}

// ================= lam scalar =================
__global__ void lam_kernel(const float* __restrict__ lq1, const float* __restrict__ lk1,
                           const float* __restrict__ lq2, const float* __restrict__ lk2,
                           const int* __restrict__ lptr)
{
    __shared__ float r1[128], r2[128];
    int t = threadIdx.x;
    r1[t] = lq1[t]*lk1[t];
    r2[t] = lq2[t]*lk2[t];
    __syncthreads();
    for (int o = 64; o; o >>= 1) {
        if (t < o) { r1[t] += r1[t+o]; r2[t] += r2[t+o]; }
        __syncthreads();
    }
    if (t == 0) {
        float lam_init = 0.8f - 0.6f*expf(-0.3f*(float)lptr[0]);
        g_scal[0] = expf(r1[0]) - expf(r2[0]) + lam_init;
        g_scal[1] = 1.0f - lam_init;
    }
}

// ================= sq / sk: warp-per-task reconstruct+normalize+scale+split ========
__global__ void __launch_bounds__(256) sqsk_kernel(const int* __restrict__ landmark,
                                                   const float* __restrict__ m1,
                                                   const float* __restrict__ m2)
{
    int task = blockIdx.x * 8 + (threadIdx.x >> 5);
    int lane = threadIdx.x & 31;
    int which = task & 1;
    int rest = task >> 1;
    int j  = rest & 63;
    int hm = (rest >> 6) % 3;
    int b  = rest / 192;
    int tok = landmark[j];

    size_t off = (size_t)(b*Tv + tok)*QKW + hm*HDv + lane*4;
    const __nv_bfloat16* ph = which ? g_kh : g_qh;
    const __nv_bfloat16* pl = which ? g_kl : g_ql;
    float v[4];
#pragma unroll
    for (int e = 0; e < 4; ++e)
        v[e] = __bfloat162float(ph[off+e]) + __bfloat162float(pl[off+e]);

    float ss = v[0]*v[0] + v[1]*v[1] + v[2]*v[2] + v[3]*v[3];
#pragma unroll
    for (int o = 16; o; o >>= 1) ss += __shfl_xor_sync(0xffffffffu, ss, o);

    float scale = (which ? m2[(hm+1)*Lv + j] : m1[(hm+1)*Lv + j]) * rsqrtf(ss);
    __nv_bfloat16* dh = which ? g_skh : g_sqh;
    __nv_bfloat16* dl = which ? g_skl : g_sql;
    size_t d = ((size_t)(b*3 + hm)*Lv + j)*HDv + lane*4;
#pragma unroll
    for (int e = 0; e < 4; ++e) {
        float o = v[e] * scale;
        __nv_bfloat16 h = __float2bfloat16(o);
        dh[d+e] = h;
        dl[d+e] = __float2bfloat16(o - __bfloat162float(h));
    }
}

// ================= symmetric mask -> per-row CSR =================
__global__ void mask_kernel(const int* __restrict__ rns)
{
    int warp = (blockIdx.x * blockDim.x + threadIdx.x) >> 5;
    int lane = threadIdx.x & 31;
    int b = warp >> 11, i = warp & (Tv-1);
    const int* row = rns + (size_t)warp * KIv;
    int j = row[lane];
    bool dup = false;
#pragma unroll
    for (int k2 = 0; k2 < 32; ++k2) {
        int jj = __shfl_sync(0xffffffffu, j, k2);
        if (k2 < lane && jj == j) dup = true;
    }
    bool mem = false;
    const int* rj = rns + (size_t)(b*Tv + j)*KIv;
#pragma unroll
    for (int m = 0; m < 32; ++m) if (rj[m] == i) mem = true;
    bool valid = (!dup) && mem;
    unsigned bal = __ballot_sync(0xffffffffu, valid);
    if (valid) {
        int pos = __popc(bal & ((1u << lane) - 1u));
        g_cols[(size_t)warp*KIv + pos] = j;
    }
    if (lane == 0) g_cnt[warp] = __popc(bal);
}

// ================= column partial sums of v (zero-nnz rows) =================
__global__ void colsumA()
{
    int g = blockIdx.x*256 + threadIdx.x;
    int chunk = g >> 10;
    int c = g & 1023;
    int b = c >> 9, col = c & 511;
    const float* p = g_v + (size_t)(b*Tv + chunk*256)*NXv + col;
    float s = 0.f;
    for (int t = 0; t < 256; ++t) s += p[(size_t)t*NXv];
    g_vpart[g] = s;
}

// ================= sparse attention: 2 rows per block ==============================
// Block 256 threads: half 0 (warps 0-3) -> row r_base+2*bid, half 1 -> +1.
// Within a half, thread t (0..127) owns dims t, t+128 (head0) and t+256, t+384 (head1).
__global__ void __launch_bounds__(256) attn_rows(const float* __restrict__ rms_g, int r_base)
{
    const int half = threadIdx.x >> 7;
    const int t = threadIdx.x & 127;
    const int r = r_base + blockIdx.x * 2 + half;
    const int b = r >> 11;
    const int i = r & (Tv-1);
    __shared__ int   scols[2][KIv];
    __shared__ float sw[2][3][KIv];
    __shared__ float cc0[2][KIv], cc1[2][KIv];
    __shared__ float red[2][2][128];
    const int cnt = g_cnt[r];
    if (t < KIv && t < cnt) scols[half][t] = g_cols[(size_t)r*KIv + t];
    __syncthreads();
    const float lam = g_scal[0];
    const int wid = (threadIdx.x >> 5) & 3;   // warp within half
    const int lane = threadIdx.x & 31;

    for (int task = wid; task < 3*cnt; task += 4) {
        int hm = task % 3, j = task / 3, h = hm + 1;
        const float* w1p = g_w1  + ((size_t)((b*4+h)*Tv + i)              << 6);
        const float* w2p = g_w2t + ((size_t)((b*4+h)*Tv + scols[half][j]) << 6);
        float s = w1p[lane]*w2p[lane] + w1p[lane+32]*w2p[lane+32];
#pragma unroll
        for (int o = 16; o; o >>= 1) s += __shfl_xor_sync(0xffffffffu, s, o);
        if (lane == 0) sw[half][hm][j] = s;
    }
    __syncthreads();

    if (wid == 0 && cnt > 0) {
        float p[3];
#pragma unroll
        for (int hm = 0; hm < 3; ++hm) {
            float x = (lane < cnt) ? sw[half][hm][lane] : -INFINITY;
            float mx = x;
#pragma unroll
            for (int o = 16; o; o >>= 1) mx = fmaxf(mx, __shfl_xor_sync(0xffffffffu, mx, o));
            float e = (lane < cnt) ? expf(x - mx) : 0.f;
            float sm = e;
#pragma unroll
            for (int o = 16; o; o >>= 1) sm += __shfl_xor_sync(0xffffffffu, sm, o);
            p[hm] = e / sm;
        }
        if (lane < cnt) {
            cc0[half][lane] = (1.f - lam)*p[1] - lam*p[0];
            cc1[half][lane] = p[1] - p[0] + (1.f - 2.f*lam)*p[2];
        }
    }
    __syncthreads();

    float s0a = 0.f, s0b = 0.f, s1a = 0.f, s1b = 0.f;
    if (cnt > 0) {
        for (int j = 0; j < cnt; ++j) {
            const float* vp = g_v + ((size_t)(b*Tv + scols[half][j]) << 9);
            float w0 = cc0[half][j], w1 = cc1[half][j];
            s0a += w0 * vp[t];
            s0b += w0 * vp[t + 128];
            s1a += w1 * vp[t + 256];
            s1b += w1 * vp[t + 384];
        }
    } else {
        float u = (1.f - 2.f*lam) * (1.f/(float)Tv);
        float t0 = 0.f, t1 = 0.f, t2 = 0.f, t3 = 0.f;
#pragma unroll
        for (int ch = 0; ch < 8; ++ch) {
            const float* vp = g_vpart + ch*1024 + b*512;
            t0 += vp[t]; t1 += vp[t+128]; t2 += vp[t+256]; t3 += vp[t+384];
        }
        s0a = u * t0; s0b = u * t1; s1a = u * t2; s1b = u * t3;
    }

    red[half][0][t] = s0a*s0a + s0b*s0b;
    red[half][1][t] = s1a*s1a + s1b*s1b;
    __syncthreads();
#pragma unroll
    for (int o = 64; o; o >>= 1) {
        if (t < o) {
            red[half][0][t] += red[half][0][t+o];
            red[half][1][t] += red[half][1][t+o];
        }
        __syncthreads();
    }
    const float onem = g_scal[1];
    const float gA = rms_g[t], gB = rms_g[t + 128];
    float sc0 = rsqrtf(red[half][0][0]*(1.f/256.f) + 1e-5f) * onem;
    float sc1 = rsqrtf(red[half][1][0]*(1.f/256.f) + 1e-5f) * onem;
    float a0 = s0a * sc0 * gA, a1 = s0b * sc0 * gB;
    float a2 = s1a * sc1 * gA, a3 = s1b * sc1 * gB;
    size_t base = (size_t)r * NXv;
    float vals[4] = {a0, a1, a2, a3};
    int offs[4] = {t, t + 128, t + 256, t + 384};
#pragma unroll
    for (int e = 0; e < 4; ++e) {
        __nv_bfloat16 h = __float2bfloat16(vals[e]);
        g_ah[base + offs[e]] = h;
        g_al[base + offs[e]] = __float2bfloat16(vals[e] - __bfloat162float(h));
    }
}

// ================= launch (multi-stream fork/join, graph-capture safe) =============
extern "C" void kernel_launch(void* const* d_in, const int* in_sizes, int n_in,
                              void* d_out, int out_size)
{
    const float* x    = (const float*)d_in[0];
    const float* wq   = (const float*)d_in[1];
    const float* wk   = (const float*)d_in[2];
    const float* wv   = (const float*)d_in[3];
    const float* wo   = (const float*)d_in[4];
    const float* m1   = (const float*)d_in[5];
    const float* m2   = (const float*)d_in[6];
    const float* lq1  = (const float*)d_in[7];
    const float* lk1  = (const float*)d_in[8];
    const float* lq2  = (const float*)d_in[9];
    const float* lk2  = (const float*)d_in[10];
    const float* rmsg = (const float*)d_in[11];
    const int*   lp   = (const int*)d_in[12];
    const int*   rns  = (const int*)d_in[14];
    const int*   lmk  = (const int*)d_in[15];
    float* out = (float*)d_out;

    static cudaStream_t s1 = nullptr, s2 = nullptr;
    static cudaEvent_t e_fork = nullptr, e_mask = nullptr, e_split = nullptr,
                       e_w = nullptr, e_cols = nullptr, e_a0 = nullptr, e_o0 = nullptr;
    static int inited = 0;
    if (!inited) {
        cudaStreamCreateWithFlags(&s1, cudaStreamNonBlocking);
        cudaStreamCreateWithFlags(&s2, cudaStreamNonBlocking);
        cudaEventCreateWithFlags(&e_fork,  cudaEventDisableTiming);
        cudaEventCreateWithFlags(&e_mask,  cudaEventDisableTiming);
        cudaEventCreateWithFlags(&e_split, cudaEventDisableTiming);
        cudaEventCreateWithFlags(&e_w,     cudaEventDisableTiming);
        cudaEventCreateWithFlags(&e_cols,  cudaEventDisableTiming);
        cudaEventCreateWithFlags(&e_a0,    cudaEventDisableTiming);
        cudaEventCreateWithFlags(&e_o0,    cudaEventDisableTiming);
        cudaFuncSetAttribute(gemm_qk,    cudaFuncAttributeMaxDynamicSharedMemorySize, GEMM_SMEM_TOTAL);
        cudaFuncSetAttribute(gemm_v,     cudaFuncAttributeMaxDynamicSharedMemorySize, GEMM_SMEM_TOTAL);
        cudaFuncSetAttribute(gemm_out,   cudaFuncAttributeMaxDynamicSharedMemorySize, GEMM_SMEM_TOTAL);
        cudaFuncSetAttribute(gemm_w_mma, cudaFuncAttributeMaxDynamicSharedMemorySize, GW_SMEM);
        inited = 1;
    }

    // fork: s1 = weight split + lam + mask (all input-only dependencies)
    cudaEventRecord(e_fork, 0);
    cudaStreamWaitEvent(s1, e_fork, 0);
    split_w<<<2048, 256, 0, s1>>>((const float2*)wq, (const float2*)wk,
                                  (const float2*)wv, (const float2*)wo);
    cudaEventRecord(e_w, s1);
    lam_kernel<<<1, 128, 0, s1>>>(lq1, lk1, lq2, lk2, lp);
    mask_kernel<<<Bv*Tv*32/256, 256, 0, s1>>>(rns);
    cudaEventRecord(e_mask, s1);

    // main: x split; then qk on main / v on s2 (both need e_w)
    split_x<<<4096, 256>>>((const float2*)x);
    cudaEventRecord(e_split, 0);

    cudaStreamWaitEvent(s2, e_split, 0);
    cudaStreamWaitEvent(s2, e_w, 0);
    gemm_v<<<dim3(Bv*Tv/64, 4), 256, GEMM_SMEM_TOTAL, s2>>>();
    colsumA<<<32, 256, 0, s2>>>();
    cudaEventRecord(e_cols, s2);

    cudaStreamWaitEvent(0, e_w, 0);
    gemm_qk<<<dim3(Bv*Tv/64, 6), 256, GEMM_SMEM_TOTAL>>>();
    sqsk_kernel<<<96, 256>>>(lmk, m1, m2);
    gemm_w_mma<<<dim3(Tv/128, Bv*3, 2), 256, GW_SMEM>>>();

    // join + pipelined attn/out: batch 0 (rows 0..2047, 1024 blocks x 2 rows) ->
    // gemm_out rows 0..2047 on s2 while batch 1 (rows 2048..4095) runs on main.
    cudaStreamWaitEvent(0, e_mask, 0);
    cudaStreamWaitEvent(0, e_cols, 0);
    attn_rows<<<Tv/2, 256>>>(rmsg, 0);
    cudaEventRecord(e_a0, 0);

    cudaStreamWaitEvent(s2, e_a0, 0);
    gemm_out<<<dim3(Tv/64, 4), 256, GEMM_SMEM_TOTAL, s2>>>(out, 0);
    cudaEventRecord(e_o0, s2);

    attn_rows<<<Tv/2, 256>>>(rmsg, Bv*Tv/2);
    gemm_out<<<dim3(Tv/64, 4), 256, GEMM_SMEM_TOTAL>>>(out, Bv*Tv/2);
    cudaStreamWaitEvent(0, e_o0, 0);
}